// round 11
// baseline (speedup 1.0000x reference)
#include <cuda_runtime.h>

// EdgeBlock monolithic: ONE CTA type does both value gather and scoring.
// B=4, L=1024, N=16, D=64, W=16, V=33.
//
// R10 lesson: two CTA types = slot-time bound (512*51us value + 512*27us
// score over 296 slots = 135us). Monolithic CTA hides score work (FMA/LDG,
// ~12us) inside the value stores' DRAM-backpressure stalls (issue was 20.5%).
//
// Each CTA: (b, 8-l tile). Stages rows l0..l0+23 (padded 1028 floats/row),
// streams 1.05 MB of value_h stores (__stcs), and computes window_score for
// all 16 heads of its 8 l's (2 heads per warp): qc via coalesced cross LDG,
// 17 deduplicated window products, leaky_relu + mask assembly.

#define Lc 1024
#define MASK_FILL -1e12f

__global__ void __launch_bounds__(256, 2) mono_kernel(
    const float* __restrict__ hidden,
    const int*   __restrict__ mask,
    const float* __restrict__ upon,
    const float* __restrict__ down,
    const float* __restrict__ cross,
    float*       __restrict__ out_ws,
    float4*      __restrict__ out_val)
{
    extern __shared__ float sm[];
    float* sh    = sm;                    // 24 rows x 1028 floats (98,688 B)
    float* su_s  = sm + 24672;            // [16][24] upon-dots, rows l0..l0+23
    float* sd_s  = su_s + 384;            // [16][24] down-dots, rows l0-16..l0+7
    float* qcs   = sd_s + 384;            // [8 warps][4][64]
    float* prs   = qcs + 2048;            // [8 warps][4][17]
    int*   smask = (int*)(prs + 544);     // [24]
    // total 28,056 floats = 112,224 B -> 2 CTAs/SM

    const int t   = threadIdx.x;          // 256 threads, 8 warps
    const int bid = blockIdx.x;           // 512 = b(4) x tile(128)
    const int b   = bid >> 7;
    const int l0  = (bid & 127) * 8;

    const float4* hidden4 = (const float4*)hidden;

    // ---- stage 24 hidden rows (full 1024 floats each, pad to 1028) ----
#pragma unroll
    for (int r = 0; r < 24; ++r) {
        int row = (l0 + r) & (Lc - 1);
        *(float4*)&sh[r * 1028 + t * 4] = hidden4[((size_t)((b << 10) + row)) * 256 + t];
    }
    if (t < 24) smask[t] = mask[(b << 10) + ((l0 + t) & (Lc - 1))];
    __syncthreads();

    // ---- su/sd: 768 dot-64 tasks (16 n x 24 rows x {su,sd}) ----
    for (int k = t; k < 768; k += 256) {
        int sdf = (k >= 384);
        int kk  = sdf ? (k - 384) : k;
        int n   = kk / 24, j = kk - n * 24;
        const float* vec = (sdf ? down : upon) + n * 64;
        float acc = 0.f;
        if (!sdf || j >= 16) {
            // row is staged: su row j, sd row (l0-16+j) = staged row (j-16)
            const float* src = &sh[(sdf ? (j - 16) : j) * 1028 + n * 64];
#pragma unroll
            for (int dq = 0; dq < 16; ++dq) {
                float4 hv = *(const float4*)&src[dq * 4];
                float4 vv = *(const float4*)&vec[dq * 4];
                acc += hv.x * vv.x + hv.y * vv.y + hv.z * vv.z + hv.w * vv.w;
            }
        } else {
            // sd rows below the tile: fetch wrapped from GMEM (L2-resident)
            int row = (l0 - 16 + j + Lc) & (Lc - 1);
            const float4* src = (const float4*)&hidden[(((size_t)(b << 10) + row) * 16 + n) * 64];
#pragma unroll
            for (int dq = 0; dq < 16; ++dq) {
                float4 hv = __ldg(&src[dq]);
                float4 vv = *(const float4*)&vec[dq * 4];
                acc += hv.x * vv.x + hv.y * vv.y + hv.z * vv.z + hv.w * vv.w;
            }
        }
        (sdf ? sd_s : su_s)[n * 24 + j] = acc;
    }
    __syncthreads();

    const int w = t >> 5, lane = t & 31;
    float* qcw = &qcs[w * 256];
    float* prw = &prs[w * 68];

    for (int half = 0; half < 2; ++half) {
        const int lh = half * 4;

        // ---- value stores for 4 l's (DRAM-write stream, __stcs) ----
        for (int i = 0; i < 4; ++i) {
            int ll = lh + i;
            size_t base = ((size_t)((b << 10) + l0 + ll)) * 33 * 256 + t;
#pragma unroll
            for (int v = 0; v < 33; ++v) {
                int off = (v <= 16) ? 0 : (v - 16);
                float4 val = *(const float4*)&sh[(ll + off) * 1028 + t * 4];
                __stcs(&out_val[base + (size_t)v * 256], val);
            }
        }

        // ---- score for 2 heads per warp, 4 l's of this half ----
        for (int n2 = 0; n2 < 2; ++n2) {
            const int n = w * 2 + n2;
            const float* cr = cross + n * 4096;

            // Phase A: qc[i][h], h = lane & lane+32. cross via coalesced LDG,
            // hidden via broadcast LDS from the shared staged rows.
            float a0[4] = {0, 0, 0, 0}, a1[4] = {0, 0, 0, 0};
#pragma unroll
            for (int dq = 0; dq < 16; ++dq) {
                float c00 = __ldg(&cr[(dq * 4 + 0) * 64 + lane]);
                float c10 = __ldg(&cr[(dq * 4 + 1) * 64 + lane]);
                float c20 = __ldg(&cr[(dq * 4 + 2) * 64 + lane]);
                float c30 = __ldg(&cr[(dq * 4 + 3) * 64 + lane]);
                float c01 = __ldg(&cr[(dq * 4 + 0) * 64 + lane + 32]);
                float c11 = __ldg(&cr[(dq * 4 + 1) * 64 + lane + 32]);
                float c21 = __ldg(&cr[(dq * 4 + 2) * 64 + lane + 32]);
                float c31 = __ldg(&cr[(dq * 4 + 3) * 64 + lane + 32]);
#pragma unroll
                for (int i = 0; i < 4; ++i) {
                    float4 hd = *(const float4*)&sh[(lh + i) * 1028 + n * 64 + dq * 4];
                    a0[i] += hd.x * c00 + hd.y * c10 + hd.z * c20 + hd.w * c30;
                    a1[i] += hd.x * c01 + hd.y * c11 + hd.z * c21 + hd.w * c31;
                }
            }
#pragma unroll
            for (int i = 0; i < 4; ++i) {
                qcw[i * 64 + lane]      = a0[i];
                qcw[i * 64 + lane + 32] = a1[i];
            }
            __syncwarp();

            // Phase B: 17 distinct window products per l (lanes 0..16)
            if (lane < 17) {
                float p[4] = {0, 0, 0, 0};
#pragma unroll
                for (int hq = 0; hq < 16; ++hq) {
#pragma unroll
                    for (int i = 0; i < 4; ++i) {
                        float4 qv = *(const float4*)&qcw[i * 64 + hq * 4];
                        float4 hv = *(const float4*)&sh[(lh + i + lane) * 1028 + n * 64 + hq * 4];
                        p[i] += qv.x * hv.x + qv.y * hv.y + qv.z * hv.z + qv.w * hv.w;
                    }
                }
#pragma unroll
                for (int i = 0; i < 4; ++i) prw[i * 17 + lane] = p[i];
            }
            __syncwarp();

            // Assembly: 33 scores per l
#pragma unroll
            for (int i = 0; i < 4; ++i) {
                int ll = lh + i, l = l0 + ll;
                size_t ob = ((size_t)((b * 16 + n) * Lc + l)) * 33;
#pragma unroll
                for (int vi = 0; vi < 2; ++vi) {
                    int v = lane + vi * 32;
                    if (v < 33) {
                        int offu = (v <= 16) ? 0 : (v - 16);
                        int offd = (v <  16) ? (v - 16) : 0;
                        float sc = prw[i * 17 + offu]
                                 + su_s[n * 24 + ll + offu]
                                 + sd_s[n * 24 + ll + offd + 16];
                        sc = (sc > 0.f) ? sc : 5.0f * sc;   // leaky_relu slope 5
                        bool m = (l + offd >= 0) && (l + offu < Lc) &&
                                 (smask[ll + offu] != 0);
                        __stcs(&out_ws[ob + v], m ? sc : MASK_FILL);
                    }
                }
            }
            __syncwarp();   // qcw/prw reused next head
        }
    }
}

extern "C" void kernel_launch(void* const* d_in, const int* in_sizes, int n_in,
                              void* d_out, int out_size) {
    const float* hidden = (const float*)d_in[0];
    const int*   mask   = (const int*)d_in[1];      // bool -> int32 on the wire
    const float* upon   = (const float*)d_in[2];
    const float* down   = (const float*)d_in[3];
    const float* cross  = (const float*)d_in[4];
    // d_in[5] (window_size) fixed at 16; compiled in.

    float*  out_ws  = (float*)d_out;
    float4* out_val = (float4*)(out_ws + (size_t)4 * 16 * Lc * 33); // 2,162,688 floats

    const int smem = 28056 * (int)sizeof(float);    // 112,224 B -> 2 CTAs/SM
    cudaFuncSetAttribute(mono_kernel, cudaFuncAttributeMaxDynamicSharedMemorySize, smem);

    mono_kernel<<<512, 256, smem>>>(hidden, mask, upon, down, cross,
                                    out_ws, out_val);
}